// round 1
// baseline (speedup 1.0000x reference)
#include <cuda_runtime.h>
#include <math.h>

#define N_PTS 16384          // 2*8192 points per cloud
#define TGT_SPLITS 8
#define TGT_PER_SPLIT (N_PTS / TGT_SPLITS)   // 2048
#define SRC_PER_BLOCK 256
#define THREADS_MAIN 128     // 2 sources per thread
#define KNN 5

// Scratch (no allocation allowed in kernel_launch)
__device__ float4 g_tgt[N_PTS];
__device__ float  g_partial[TGT_SPLITS * N_PTS * KNN];  // [split][src][k]
__device__ double g_acc;
__device__ int    g_cnt;

// ---------------------------------------------------------------------------
// Prep: transform targets to (-2x, -2y, -2z, |t|^2); invalid targets -> 1e20.
// Also zero the accumulators (graph-replayed every call).
// ---------------------------------------------------------------------------
__global__ void prep_kernel(const float* __restrict__ tgt) {
    int i = blockIdx.x * blockDim.x + threadIdx.x;
    if (i == 0) { g_acc = 0.0; g_cnt = 0; }
    if (i < N_PTS) {
        float x = tgt[3 * i + 0];
        float y = tgt[3 * i + 1];
        float z = tgt[3 * i + 2];
        bool valid = (x != 0.0f) || (y != 0.0f) || (z != 0.0f);
        float t2 = fmaf(x, x, fmaf(y, y, z * z));
        float4 v;
        if (valid) {
            v.x = -2.0f * x; v.y = -2.0f * y; v.z = -2.0f * z; v.w = t2;
        } else {
            v.x = 0.0f; v.y = 0.0f; v.z = 0.0f; v.w = 1e20f;  // -> d ~ 1e10 (BIG)
        }
        g_tgt[i] = v;
    }
}

// Branchless sorted insert (ascending m0..m4). Precondition: q < m4.
__device__ __forceinline__ void insert5(float q, float& m0, float& m1,
                                        float& m2, float& m3, float& m4) {
    m4 = fmaxf(m3, q);
    m3 = fminf(m3, fmaxf(m2, q));
    m2 = fminf(m2, fmaxf(m1, q));
    m1 = fminf(m1, fmaxf(m0, q));
    m0 = fminf(m0, q);
}

// ---------------------------------------------------------------------------
// Main: each block = 256 sources x 2048 targets (one smem tile).
// Each thread handles 2 sources; per target: 1 broadcast LDS.128 + 6 FFMA + 2 cmp.
// Maintains top-5 of q = t^2 - 2 s.t (order-equivalent to d^2).
// ---------------------------------------------------------------------------
__global__ __launch_bounds__(THREADS_MAIN)
void knn_main_kernel(const float* __restrict__ src) {
    __shared__ float4 s_tgt[TGT_PER_SPLIT];   // 32 KB

    const int split = blockIdx.y;
    const int tgt0  = split * TGT_PER_SPLIT;

    for (int i = threadIdx.x; i < TGT_PER_SPLIT; i += THREADS_MAIN)
        s_tgt[i] = g_tgt[tgt0 + i];
    __syncthreads();

    const int s0 = blockIdx.x * SRC_PER_BLOCK + threadIdx.x;
    const int s1 = s0 + THREADS_MAIN;

    const float ax = src[3 * s0 + 0], ay = src[3 * s0 + 1], az = src[3 * s0 + 2];
    const float bx = src[3 * s1 + 0], by = src[3 * s1 + 1], bz = src[3 * s1 + 2];

    float a0 = 1e30f, a1 = 1e30f, a2 = 1e30f, a3 = 1e30f, a4 = 1e30f;
    float b0 = 1e30f, b1 = 1e30f, b2 = 1e30f, b3 = 1e30f, b4 = 1e30f;

#pragma unroll 4
    for (int t = 0; t < TGT_PER_SPLIT; ++t) {
        float4 v = s_tgt[t];
        float qa = fmaf(ax, v.x, fmaf(ay, v.y, fmaf(az, v.z, v.w)));
        float qb = fmaf(bx, v.x, fmaf(by, v.y, fmaf(bz, v.z, v.w)));
        if (qa < a4) insert5(qa, a0, a1, a2, a3, a4);
        if (qb < b4) insert5(qb, b0, b1, b2, b3, b4);
    }

    float* pa = &g_partial[(split * N_PTS + s0) * KNN];
    pa[0] = a0; pa[1] = a1; pa[2] = a2; pa[3] = a3; pa[4] = a4;
    float* pb = &g_partial[(split * N_PTS + s1) * KNN];
    pb[0] = b0; pb[1] = b1; pb[2] = b2; pb[3] = b3; pb[4] = b4;
}

// ---------------------------------------------------------------------------
// Merge: per source fold 8 partial top-5 lists -> global top-5, add s^2,
// sqrt, mask invalid sources, block-reduce, atomic into double accumulator.
// ---------------------------------------------------------------------------
__global__ void merge_kernel(const float* __restrict__ src) {
    const int s   = blockIdx.x * blockDim.x + threadIdx.x;
    const int tid = threadIdx.x;

    float m0 = 1e30f, m1 = 1e30f, m2 = 1e30f, m3 = 1e30f, m4 = 1e30f;
#pragma unroll
    for (int p = 0; p < TGT_SPLITS; ++p) {
        const float* q = &g_partial[(p * N_PTS + s) * KNN];
#pragma unroll
        for (int j = 0; j < KNN; ++j) {
            float v = q[j];
            if (v < m4) insert5(v, m0, m1, m2, m3, m4);
        }
    }

    const float x = src[3 * s + 0], y = src[3 * s + 1], z = src[3 * s + 2];
    const float s2 = fmaf(x, x, fmaf(y, y, z * z));
    const bool valid = (x != 0.0f) || (y != 0.0f) || (z != 0.0f);

    float sum = sqrtf(fmaxf(m0 + s2, 1e-12f))
              + sqrtf(fmaxf(m1 + s2, 1e-12f))
              + sqrtf(fmaxf(m2 + s2, 1e-12f))
              + sqrtf(fmaxf(m3 + s2, 1e-12f))
              + sqrtf(fmaxf(m4 + s2, 1e-12f));
    sum = valid ? sum : 0.0f;

    __shared__ float sred[256];
    __shared__ int   cred[256];
    sred[tid] = sum;
    cred[tid] = valid ? 1 : 0;
    __syncthreads();
#pragma unroll
    for (int off = 128; off > 0; off >>= 1) {
        if (tid < off) {
            sred[tid] += sred[tid + off];
            cred[tid] += cred[tid + off];
        }
        __syncthreads();
    }
    if (tid == 0) {
        atomicAdd(&g_acc, (double)sred[0]);
        atomicAdd(&g_cnt, cred[0]);
    }
}

__global__ void finalize_kernel(float* __restrict__ out) {
    double denom = (double)g_cnt * (double)KNN;
    out[0] = (float)(g_acc / denom);
}

// ---------------------------------------------------------------------------
extern "C" void kernel_launch(void* const* d_in, const int* in_sizes, int n_in,
                              void* d_out, int out_size) {
    const float* src = (const float*)d_in[0];  // source_pc (2,8192,3)
    const float* tgt = (const float*)d_in[1];  // target_pc (2,8192,3)
    float* out = (float*)d_out;

    prep_kernel<<<N_PTS / 256, 256>>>(tgt);

    dim3 grid(N_PTS / SRC_PER_BLOCK, TGT_SPLITS);   // (64, 8) = 512 blocks
    knn_main_kernel<<<grid, THREADS_MAIN>>>(src);

    merge_kernel<<<N_PTS / 256, 256>>>(src);
    finalize_kernel<<<1, 1>>>(out);
}